// round 8
// baseline (speedup 1.0000x reference)
#include <cuda_runtime.h>

#define NJ   24
#define TPB  192
#define NG   64            // node-groups per block (TPB/3)
#define NPT  6             // nodes per thread
#define NPB  (NG * NPT)    // 384 nodes = 16 frames per block
#define RS   28            // sH row stride (floats): h[24] + a_src[3] + pad
#define NEG  0.2f

typedef unsigned long long ull;

__constant__ int c_parent[NJ] = {-1,0,0,0,1,2,3,4,5,6,7,8,9,9,9,12,13,14,16,17,18,19,20,21};
#define PARENT_MASK 0x3F73FFu   // joints that are some child's parent

__device__ __forceinline__ void fma2(ull &d, ull a, ull b) {
    asm("fma.rn.f32x2 %0, %1, %2, %0;" : "+l"(d) : "l"(a), "l"(b));
}
__device__ __forceinline__ ull pack2(float x) {
    ull r; asm("mov.b64 %0, {%1, %1};" : "=l"(r) : "f"(x)); return r;
}
__device__ __forceinline__ ull packf2(float lo, float hi) {
    ull r; asm("mov.b64 %0, {%1, %2};" : "=l"(r) : "f"(lo), "f"(hi)); return r;
}
__device__ __forceinline__ float2 unpack2(ull v) {
    float2 f; asm("mov.b64 {%0, %1}, %2;" : "=f"(f.x), "=f"(f.y) : "l"(v)); return f;
}

__global__ __launch_bounds__(TPB, 3)
void gat_encoder_kernel(const float* __restrict__ src,
                        const float* __restrict__ Wpre,   // (3,24)
                        const float* __restrict__ bpre,   // (24)
                        const float* __restrict__ Wg,     // (24,24)
                        const float* __restrict__ attS,   // (3,8)
                        const float* __restrict__ attD,   // (3,8)
                        const float* __restrict__ bg,     // (24)
                        float* __restrict__ out)
{
    __shared__ __align__(16) float sWg[576];
    __shared__ __align__(16) ull   sP2[96];   // per channel k: {w0,w0},{w1,w1},{w2,w2},{b,b}
    __shared__ __align__(16) float sAttS[24];
    __shared__ __align__(16) float sAttD[24];
    __shared__ __align__(16) float sbg[24];
    __shared__ __align__(16) float sH[NPB * RS];

    const int t  = threadIdx.x;
    const int cg = t % 3;          // head: channels 8cg..8cg+7
    const int g  = t / 3;          // node group 0..63

    // ---- stage weights; Wpre/bias pre-broadcast as {v,v} pairs ----
    if (t < 96) {
        const int ch = t >> 2, r = t & 3;
        const float v = (r < 3) ? Wpre[r * 24 + ch] : bpre[ch];
        sP2[ch * 4 + r] = pack2(v);
    }
    if (t < 24) { sAttS[t] = attS[t]; sAttD[t] = attD[t]; sbg[t] = bg[t]; }
    for (int i = t; i < 576; i += TPB) sWg[i] = Wg[i];

    const size_t base = (size_t)blockIdx.x * NPB;

    // ---- inputs: packed over node pairs (2p, 2p+1) ----
    ull pin0[3], pin1[3], pin2[3];
    #pragma unroll
    for (int p = 0; p < 3; p++) {
        const float* pa = src + (base + (size_t)(g + 64 * (2*p    ))) * 3;
        const float* pb = src + (base + (size_t)(g + 64 * (2*p + 1))) * 3;
        const float a0 = pa[0], a1 = pa[1], a2 = pa[2];
        const float b0 = pb[0], b1 = pb[1], b2 = pb[2];
        pin0[p] = packf2(a0, b0);
        pin1[p] = packf2(a1, b1);
        pin2[p] = packf2(a2, b2);
    }

    __syncthreads();

    // ---- fused phase1+2: per k, build x[k] for all 6 nodes, feed GEMM ----
    ull acc[NPT][4];
    #pragma unroll
    for (int i = 0; i < NPT; i++)
        #pragma unroll
        for (int q = 0; q < 4; q++) acc[i][q] = 0ull;

    #pragma unroll
    for (int k = 0; k < 24; k++) {
        const ulonglong2* pp = (const ulonglong2*)(sP2 + k * 4);
        const ulonglong2 q0 = pp[0], q1 = pp[1];   // {w0,w0},{w1,w1} / {w2,w2},{b,b}
        const ulonglong2* wr = (const ulonglong2*)(sWg + k * 24 + 8 * cg);
        const ulonglong2 wA = wr[0], wB = wr[1];   // Wg[k, my 8 channels]
        #pragma unroll
        for (int p = 0; p < 3; p++) {
            ull xc = q1.y;                         // bias pair
            fma2(xc, pin0[p], q0.x);
            fma2(xc, pin1[p], q0.y);
            fma2(xc, pin2[p], q1.x);
            const float2 f = unpack2(xc);          // lanes = nodes 2p, 2p+1
            const ull xi = pack2(fmaxf(f.x, 0.0f));
            const ull xj = pack2(fmaxf(f.y, 0.0f));
            fma2(acc[2*p    ][0], xi, wA.x); fma2(acc[2*p    ][1], xi, wA.y);
            fma2(acc[2*p    ][2], xi, wB.x); fma2(acc[2*p    ][3], xi, wB.y);
            fma2(acc[2*p + 1][0], xj, wA.x); fma2(acc[2*p + 1][1], xj, wA.y);
            fma2(acc[2*p + 1][2], xj, wB.x); fma2(acc[2*p + 1][3], xj, wB.y);
        }
    }

    // ---- attention dots for my head ----
    float aS[NPT], aD[NPT];
    {
        const ulonglong2 sa = ((const ulonglong2*)sAttS)[2*cg];
        const ulonglong2 sb = ((const ulonglong2*)sAttS)[2*cg + 1];
        const ulonglong2 da = ((const ulonglong2*)sAttD)[2*cg];
        const ulonglong2 db = ((const ulonglong2*)sAttD)[2*cg + 1];
        #pragma unroll
        for (int i = 0; i < NPT; i++) {
            ull r1 = 0ull, r2 = 0ull;
            fma2(r1, acc[i][0], sa.x); fma2(r1, acc[i][1], sa.y);
            fma2(r1, acc[i][2], sb.x); fma2(r1, acc[i][3], sb.y);
            fma2(r2, acc[i][0], da.x); fma2(r2, acc[i][1], da.y);
            fma2(r2, acc[i][2], db.x); fma2(r2, acc[i][3], db.y);
            const float2 f1 = unpack2(r1), f2 = unpack2(r2);
            aS[i] = f1.x + f1.y;
            aD[i] = f2.x + f2.y;
        }
    }

    // ---- publish h + a_src (only joints that are parents) ----
    #pragma unroll
    for (int i = 0; i < NPT; i++) {
        const int row = g + 64*i;
        const int j = row % NJ;
        if ((PARENT_MASK >> j) & 1u) {
            ulonglong2* hr = (ulonglong2*)(sH + row * RS + 8*cg);
            ulonglong2 v0, v1;
            v0.x = acc[i][0]; v0.y = acc[i][1];
            v1.x = acc[i][2]; v1.y = acc[i][3];
            hr[0] = v0; hr[1] = v1;
            sH[row * RS + 24 + cg] = aS[i];
        }
    }
    __syncthreads();

    // ---- epilogue: 2-edge softmax + aggregate + bias + relu + store ----
    const ulonglong2 bgA = ((const ulonglong2*)sbg)[2*cg];
    const ulonglong2 bgB = ((const ulonglong2*)sbg)[2*cg + 1];
    #pragma unroll
    for (int i = 0; i < NPT; i++) {
        const int row = g + 64*i;
        const int j = row % NJ;
        const int par = c_parent[j];
        const bool hasPar = (par >= 0);
        const int prow = row - j + (hasPar ? par : j);
        const float* pb = sH + prow * RS;
        const ulonglong2* ph = (const ulonglong2*)(pb + 8*cg);
        const ulonglong2 ph0 = ph[0], ph1 = ph[1];
        const float pas = pb[24 + cg];

        float es = aS[i] + aD[i];
        es = es >= 0.0f ? es : NEG * es;
        float ep = pas + aD[i];
        ep = ep >= 0.0f ? ep : NEG * ep;
        ep = hasPar ? ep : -1e30f;
        const float mx  = fmaxf(es, ep);
        const float ws  = __expf(es - mx);
        const float wp  = __expf(ep - mx);
        const float inv = __fdividef(1.0f, ws + wp);
        const float alS = ws * inv;
        const float alP = hasPar ? wp * inv : 0.0f;

        const ull s2 = pack2(alS), pp = pack2(alP);
        ull o0 = bgA.x, o1 = bgA.y, o2 = bgB.x, o3 = bgB.y;
        fma2(o0, s2, acc[i][0]); fma2(o0, pp, ph0.x);
        fma2(o1, s2, acc[i][1]); fma2(o1, pp, ph0.y);
        fma2(o2, s2, acc[i][2]); fma2(o2, pp, ph1.x);
        fma2(o3, s2, acc[i][3]); fma2(o3, pp, ph1.y);

        const float2 f0 = unpack2(o0), f1 = unpack2(o1), f2 = unpack2(o2), f3 = unpack2(o3);
        float4* op = (float4*)(out + (base + (size_t)row) * 24 + 8*cg);
        float4 r0, r1;
        r0.x = fmaxf(f0.x, 0.f); r0.y = fmaxf(f0.y, 0.f);
        r0.z = fmaxf(f1.x, 0.f); r0.w = fmaxf(f1.y, 0.f);
        r1.x = fmaxf(f2.x, 0.f); r1.y = fmaxf(f2.y, 0.f);
        r1.z = fmaxf(f3.x, 0.f); r1.w = fmaxf(f3.y, 0.f);
        op[0] = r0; op[1] = r1;
    }
}

extern "C" void kernel_launch(void* const* d_in, const int* in_sizes, int n_in,
                              void* d_out, int out_size) {
    (void)n_in; (void)out_size;
    const float* src  = (const float*)d_in[0];
    const float* Wpre = (const float*)d_in[1];
    const float* bpre = (const float*)d_in[2];
    const float* Wg   = (const float*)d_in[3];
    const float* attS = (const float*)d_in[4];
    const float* attD = (const float*)d_in[5];
    const float* bg   = (const float*)d_in[6];

    const int nodes  = in_sizes[0] / 3;   // 3,145,728
    const int blocks = nodes / NPB;       // 8,192 (exact)

    gat_encoder_kernel<<<blocks, TPB>>>(src, Wpre, bpre, Wg, attS, attD, bg, (float*)d_out);
}

// round 9
// speedup vs baseline: 1.1892x; 1.1892x over previous
#include <cuda_runtime.h>

#define NJ   24
#define TPB  192
#define NPB  (TPB * 2)     // 384 nodes = 16 frames per block; thread owns nodes t, t+192
#define RS   28            // sH row stride (floats): h[24] + a_src[3] + pad
#define NEG  0.2f

typedef unsigned long long ull;

__constant__ int c_parent[NJ] = {-1,0,0,0,1,2,3,4,5,6,7,8,9,9,9,12,13,14,16,17,18,19,20,21};
#define PARENT_MASK 0x3F73FFu   // joints that are some child's parent

__device__ __forceinline__ void fma2(ull &d, ull a, ull b) {
    asm("fma.rn.f32x2 %0, %1, %2, %0;" : "+l"(d) : "l"(a), "l"(b));
}
__device__ __forceinline__ ull pack2(float x) {
    ull r; asm("mov.b64 %0, {%1, %1};" : "=l"(r) : "f"(x)); return r;
}
__device__ __forceinline__ ull packf2(float lo, float hi) {
    ull r; asm("mov.b64 %0, {%1, %2};" : "=l"(r) : "f"(lo), "f"(hi)); return r;
}
__device__ __forceinline__ float2 unpack2(ull v) {
    float2 f; asm("mov.b64 {%0, %1}, %2;" : "=f"(f.x), "=f"(f.y) : "l"(v)); return f;
}

// epilogue for one node: 2-edge softmax + aggregate + bias + relu + store
__device__ __forceinline__ void finish_node(const ull* __restrict__ acc,   // 12 ch-pairs
                                            const float* __restrict__ aS,  // [3]
                                            const float* __restrict__ aD,  // [3]
                                            const float* __restrict__ prow,
                                            bool hasPar,
                                            const ull* __restrict__ bgp,   // 12 bias pairs
                                            float* __restrict__ outp)
{
    const ulonglong2* p2 = (const ulonglong2*)prow;
    ulonglong2 pr[6];
    #pragma unroll
    for (int q = 0; q < 6; q++) pr[q] = p2[q];         // parent h as 12 ch-pairs
    const float pas0 = prow[24], pas1 = prow[25], pas2 = prow[26];
    const float pasv[3] = {pas0, pas1, pas2};

    float alS[3], alP[3];
    #pragma unroll
    for (int hh = 0; hh < 3; hh++) {
        float es = aS[hh] + aD[hh];
        es = es >= 0.0f ? es : NEG * es;
        float ep = pasv[hh] + aD[hh];
        ep = ep >= 0.0f ? ep : NEG * ep;
        ep = hasPar ? ep : -1e30f;
        const float mx  = fmaxf(es, ep);
        const float ws  = __expf(es - mx);
        const float wp  = __expf(ep - mx);
        const float inv = __fdividef(1.0f, ws + wp);
        alS[hh] = ws * inv;
        alP[hh] = hasPar ? wp * inv : 0.0f;
    }

    float4* o4 = (float4*)outp;
    #pragma unroll
    for (int v = 0; v < 6; v++) {                       // 2 ch-pairs per float4
        const int q0 = 2*v, q1 = 2*v + 1;
        const int hh = v >> 1;
        const ull s2 = pack2(alS[hh]);
        const ull p2k = pack2(alP[hh]);
        ull o0 = bgp[q0], o1 = bgp[q1];
        const ull ph0 = (q0 & 1) ? pr[q0 >> 1].y : pr[q0 >> 1].x;
        const ull ph1 = (q1 & 1) ? pr[q1 >> 1].y : pr[q1 >> 1].x;
        fma2(o0, s2, acc[q0]); fma2(o0, p2k, ph0);
        fma2(o1, s2, acc[q1]); fma2(o1, p2k, ph1);
        const float2 f0 = unpack2(o0), f1 = unpack2(o1);
        float4 r;
        r.x = fmaxf(f0.x, 0.f); r.y = fmaxf(f0.y, 0.f);
        r.z = fmaxf(f1.x, 0.f); r.w = fmaxf(f1.y, 0.f);
        o4[v] = r;
    }
}

__global__ __launch_bounds__(TPB, 3)
void gat_encoder_kernel(const float* __restrict__ src,
                        const float* __restrict__ Wpre,   // (3,24)
                        const float* __restrict__ bpre,   // (24)
                        const float* __restrict__ Wg,     // (24,24)
                        const float* __restrict__ attS,   // (3,8)
                        const float* __restrict__ attD,   // (3,8)
                        const float* __restrict__ bg,     // (24)
                        float* __restrict__ out)
{
    __shared__ __align__(16) float sWg[576];
    __shared__ __align__(16) ull   sP2[96];    // per channel: {w0,w0},{w1,w1},{w2,w2},{b,b}
    __shared__ __align__(16) float sAttS[24];
    __shared__ __align__(16) float sAttD[24];
    __shared__ __align__(16) float sbg[24];
    __shared__ __align__(16) float sH[NPB * RS];

    const int t = threadIdx.x;
    const int j = t % NJ;

    if (t < 96) {
        const int ch = t >> 2, r = t & 3;
        const float v = (r < 3) ? Wpre[r * 24 + ch] : bpre[ch];
        sP2[ch * 4 + r] = pack2(v);
    }
    if (t < 24) { sAttS[t] = attS[t]; sAttD[t] = attD[t]; sbg[t] = bg[t]; }
    for (int i = t; i < 576; i += TPB) sWg[i] = Wg[i];

    const size_t base = (size_t)blockIdx.x * NPB;

    // ---- inputs: node pair (t, t+192) packed per input channel ----
    const float* pA = src + (base + (size_t)t) * 3;
    const float* pB = src + (base + (size_t)(t + TPB)) * 3;
    const float a0 = pA[0], a1 = pA[1], a2 = pA[2];
    const float b0 = pB[0], b1 = pB[1], b2 = pB[2];
    const ull pin0 = packf2(a0, b0);
    const ull pin1 = packf2(a1, b1);
    const ull pin2 = packf2(a2, b2);

    __syncthreads();

    // ---- fused: per k, x[k] for both nodes (one packed fma chain), feed 24-ch GEMM ----
    ull accA[12], accB[12];   // channel pairs for node t / node t+192
    #pragma unroll
    for (int q = 0; q < 12; q++) { accA[q] = 0ull; accB[q] = 0ull; }

    #pragma unroll
    for (int k = 0; k < 24; k++) {
        const ulonglong2* pp = (const ulonglong2*)(sP2 + k * 4);
        const ulonglong2 q0 = pp[0], q1 = pp[1];
        ull xc = q1.y;                          // bias pair
        fma2(xc, pin0, q0.x);
        fma2(xc, pin1, q0.y);
        fma2(xc, pin2, q1.x);
        const float2 f = unpack2(xc);
        const ull xi = pack2(fmaxf(f.x, 0.0f)); // node t
        const ull xj = pack2(fmaxf(f.y, 0.0f)); // node t+192

        const ulonglong2* wr = (const ulonglong2*)(sWg + k * 24);
        const ulonglong2 w0 = wr[0], w1 = wr[1], w2 = wr[2];   // 6 ch-pairs
        fma2(accA[0], xi, w0.x); fma2(accA[1], xi, w0.y);
        fma2(accA[2], xi, w1.x); fma2(accA[3], xi, w1.y);
        fma2(accA[4], xi, w2.x); fma2(accA[5], xi, w2.y);
        fma2(accB[0], xj, w0.x); fma2(accB[1], xj, w0.y);
        fma2(accB[2], xj, w1.x); fma2(accB[3], xj, w1.y);
        fma2(accB[4], xj, w2.x); fma2(accB[5], xj, w2.y);
        const ulonglong2* wr2 = wr + 3;
        const ulonglong2 w3 = wr2[0], w4 = wr2[1], w5 = wr2[2];
        fma2(accA[6],  xi, w3.x); fma2(accA[7],  xi, w3.y);
        fma2(accA[8],  xi, w4.x); fma2(accA[9],  xi, w4.y);
        fma2(accA[10], xi, w5.x); fma2(accA[11], xi, w5.y);
        fma2(accB[6],  xj, w3.x); fma2(accB[7],  xj, w3.y);
        fma2(accB[8],  xj, w4.x); fma2(accB[9],  xj, w4.y);
        fma2(accB[10], xj, w5.x); fma2(accB[11], xj, w5.y);
    }

    // ---- attention dots, all 3 heads, both nodes ----
    float aSA[3], aDA[3], aSB[3], aDB[3];
    {
        const ulonglong2* S2 = (const ulonglong2*)sAttS;
        const ulonglong2* D2 = (const ulonglong2*)sAttD;
        #pragma unroll
        for (int hh = 0; hh < 3; hh++) {
            const ulonglong2 sa = S2[2*hh], sb = S2[2*hh + 1];
            const ulonglong2 da = D2[2*hh], db = D2[2*hh + 1];
            ull rSA = 0ull, rDA = 0ull, rSB = 0ull, rDB = 0ull;
            fma2(rSA, accA[4*hh],   sa.x); fma2(rSA, accA[4*hh+1], sa.y);
            fma2(rSA, accA[4*hh+2], sb.x); fma2(rSA, accA[4*hh+3], sb.y);
            fma2(rDA, accA[4*hh],   da.x); fma2(rDA, accA[4*hh+1], da.y);
            fma2(rDA, accA[4*hh+2], db.x); fma2(rDA, accA[4*hh+3], db.y);
            fma2(rSB, accB[4*hh],   sa.x); fma2(rSB, accB[4*hh+1], sa.y);
            fma2(rSB, accB[4*hh+2], sb.x); fma2(rSB, accB[4*hh+3], sb.y);
            fma2(rDB, accB[4*hh],   da.x); fma2(rDB, accB[4*hh+1], da.y);
            fma2(rDB, accB[4*hh+2], db.x); fma2(rDB, accB[4*hh+3], db.y);
            float2 f;
            f = unpack2(rSA); aSA[hh] = f.x + f.y;
            f = unpack2(rDA); aDA[hh] = f.x + f.y;
            f = unpack2(rSB); aSB[hh] = f.x + f.y;
            f = unpack2(rDB); aDB[hh] = f.x + f.y;
        }
    }

    // ---- publish h + a_src (only parent joints) ----
    if ((PARENT_MASK >> j) & 1u) {
        ulonglong2* r0 = (ulonglong2*)(sH + t * RS);
        ulonglong2* r1 = (ulonglong2*)(sH + (t + TPB) * RS);
        #pragma unroll
        for (int q = 0; q < 6; q++) {
            ulonglong2 va; va.x = accA[2*q]; va.y = accA[2*q + 1]; r0[q] = va;
            ulonglong2 vb; vb.x = accB[2*q]; vb.y = accB[2*q + 1]; r1[q] = vb;
        }
        float* f0 = sH + t * RS;
        float* f1 = sH + (t + TPB) * RS;
        f0[24] = aSA[0]; f0[25] = aSA[1]; f0[26] = aSA[2];
        f1[24] = aSB[0]; f1[25] = aSB[1]; f1[26] = aSB[2];
    }
    __syncthreads();

    // ---- epilogue ----
    const int par = c_parent[j];
    const bool hasPar = (par >= 0);
    const int pt = (t - j) + (hasPar ? par : j);

    ull bgp[12];
    {
        const ulonglong2* b2 = (const ulonglong2*)sbg;
        #pragma unroll
        for (int v = 0; v < 6; v++) { bgp[2*v] = b2[v].x; bgp[2*v + 1] = b2[v].y; }
    }

    finish_node(accA, aSA, aDA, sH + pt * RS,         hasPar, bgp, out + (base + (size_t)t) * 24);
    finish_node(accB, aSB, aDB, sH + (pt + TPB) * RS, hasPar, bgp, out + (base + (size_t)(t + TPB)) * 24);
}

extern "C" void kernel_launch(void* const* d_in, const int* in_sizes, int n_in,
                              void* d_out, int out_size) {
    (void)n_in; (void)out_size;
    const float* src  = (const float*)d_in[0];
    const float* Wpre = (const float*)d_in[1];
    const float* bpre = (const float*)d_in[2];
    const float* Wg   = (const float*)d_in[3];
    const float* attS = (const float*)d_in[4];
    const float* attD = (const float*)d_in[5];
    const float* bg   = (const float*)d_in[6];

    const int nodes  = in_sizes[0] / 3;   // 3,145,728
    const int blocks = nodes / NPB;       // 8,192 (exact)

    gat_encoder_kernel<<<blocks, TPB>>>(src, Wpre, bpre, Wg, attS, attD, bg, (float*)d_out);
}

// round 11
// speedup vs baseline: 1.2991x; 1.0925x over previous
#include <cuda_runtime.h>

#define NJ   24
#define TPB  192
#define NPB  (TPB * 2)     // 384 nodes = 16 frames per block; thread owns nodes t, t+192
#define RS   28            // sH row stride (floats): h[24] + a_src[3] + pad
#define NEG  0.2f

typedef unsigned long long ull;

__constant__ int c_parent[NJ] = {-1,0,0,0,1,2,3,4,5,6,7,8,9,9,9,12,13,14,16,17,18,19,20,21};
#define PARENT_MASK 0x3F73FFu   // joints that are some child's parent

__device__ __forceinline__ void fma2(ull &d, ull a, ull b) {
    asm("fma.rn.f32x2 %0, %1, %2, %0;" : "+l"(d) : "l"(a), "l"(b));
}
__device__ __forceinline__ ull pack2(float x) {
    ull r; asm("mov.b64 %0, {%1, %1};" : "=l"(r) : "f"(x)); return r;
}
__device__ __forceinline__ ull packf2(float lo, float hi) {
    ull r; asm("mov.b64 %0, {%1, %2};" : "=l"(r) : "f"(lo), "f"(hi)); return r;
}
__device__ __forceinline__ float2 unpack2(ull v) {
    float2 f; asm("mov.b64 {%0, %1}, %2;" : "=f"(f.x), "=f"(f.y) : "l"(v)); return f;
}

// epilogue for one node: 2-edge softmax + aggregate + bias + relu + store
__device__ __forceinline__ void finish_node(const ull* __restrict__ acc,   // 12 ch-pairs
                                            const float* __restrict__ aS,  // [3]
                                            const float* __restrict__ aD,  // [3]
                                            const float* __restrict__ prow,
                                            bool hasPar,
                                            const ull* __restrict__ bgp,   // 12 bias pairs
                                            float* __restrict__ outp)
{
    const ulonglong2* p2 = (const ulonglong2*)prow;
    ulonglong2 pr[6];
    #pragma unroll
    for (int q = 0; q < 6; q++) pr[q] = p2[q];         // parent h as 12 ch-pairs
    const float pasv[3] = {prow[24], prow[25], prow[26]};

    float alS[3], alP[3];
    #pragma unroll
    for (int hh = 0; hh < 3; hh++) {
        float es = aS[hh] + aD[hh];
        es = es >= 0.0f ? es : NEG * es;
        float ep = pasv[hh] + aD[hh];
        ep = ep >= 0.0f ? ep : NEG * ep;
        ep = hasPar ? ep : -1e30f;
        const float mx  = fmaxf(es, ep);
        const float ws  = __expf(es - mx);
        const float wp  = __expf(ep - mx);
        const float inv = __fdividef(1.0f, ws + wp);
        alS[hh] = ws * inv;
        alP[hh] = hasPar ? wp * inv : 0.0f;
    }

    float4* o4 = (float4*)outp;
    #pragma unroll
    for (int v = 0; v < 6; v++) {                       // 2 ch-pairs per float4
        const int q0 = 2*v, q1 = 2*v + 1;
        const int hh = v >> 1;
        const ull s2 = pack2(alS[hh]);
        const ull p2k = pack2(alP[hh]);
        ull o0 = bgp[q0], o1 = bgp[q1];
        const ull ph0 = (q0 & 1) ? pr[q0 >> 1].y : pr[q0 >> 1].x;
        const ull ph1 = (q1 & 1) ? pr[q1 >> 1].y : pr[q1 >> 1].x;
        fma2(o0, s2, acc[q0]); fma2(o0, p2k, ph0);
        fma2(o1, s2, acc[q1]); fma2(o1, p2k, ph1);
        const float2 f0 = unpack2(o0), f1 = unpack2(o1);
        float4 r;
        r.x = fmaxf(f0.x, 0.f); r.y = fmaxf(f0.y, 0.f);
        r.z = fmaxf(f1.x, 0.f); r.w = fmaxf(f1.y, 0.f);
        o4[v] = r;
    }
}

__global__ __launch_bounds__(TPB, 4)
void gat_encoder_kernel(const float* __restrict__ src,
                        const float* __restrict__ Wpre,   // (3,24)
                        const float* __restrict__ bpre,   // (24)
                        const float* __restrict__ Wg,     // (24,24)
                        const float* __restrict__ attS,   // (3,8)
                        const float* __restrict__ attD,   // (3,8)
                        const float* __restrict__ bg,     // (24)
                        float* __restrict__ out)
{
    __shared__ __align__(16) float sWg[576];
    __shared__ __align__(16) float sPre[96];   // per channel k: {w0, w1, w2, b} raw floats
    __shared__ __align__(16) float sAttS[24];
    __shared__ __align__(16) float sAttD[24];
    __shared__ __align__(16) float sbg[24];
    __shared__ __align__(16) float sH[NPB * RS];

    const int t = threadIdx.x;
    const int j = t % NJ;

    if (t < 96) {
        const int ch = t >> 2, r = t & 3;
        sPre[t] = (r < 3) ? Wpre[r * 24 + ch] : bpre[ch];
    }
    if (t < 24) { sAttS[t] = attS[t]; sAttD[t] = attD[t]; sbg[t] = bg[t]; }
    for (int i = t; i < 576; i += TPB) sWg[i] = Wg[i];

    const size_t base = (size_t)blockIdx.x * NPB;

    // ---- inputs: node pair (t, t+192) packed per input channel ----
    const float* pA = src + (base + (size_t)t) * 3;
    const float* pB = src + (base + (size_t)(t + TPB)) * 3;
    const float a0 = pA[0], a1 = pA[1], a2 = pA[2];
    const float b0 = pB[0], b1 = pB[1], b2 = pB[2];
    const ull pin0 = packf2(a0, b0);
    const ull pin1 = packf2(a1, b1);
    const ull pin2 = packf2(a2, b2);

    __syncthreads();

    // ---- fused: per k, x[k] for both nodes (one packed fma chain), feed 24-ch GEMM ----
    ull accA[12], accB[12];   // channel pairs for node t / node t+192
    #pragma unroll
    for (int q = 0; q < 12; q++) { accA[q] = 0ull; accB[q] = 0ull; }

    #pragma unroll
    for (int k = 0; k < 24; k++) {
        const float4 pw = ((const float4*)sPre)[k];    // {w0, w1, w2, b}
        ull xc = pack2(pw.w);                          // bias pair
        fma2(xc, pin0, pack2(pw.x));
        fma2(xc, pin1, pack2(pw.y));
        fma2(xc, pin2, pack2(pw.z));
        const float2 f = unpack2(xc);
        const ull xi = pack2(fmaxf(f.x, 0.0f));        // node t
        const ull xj = pack2(fmaxf(f.y, 0.0f));        // node t+192

        const ulonglong2* wr = (const ulonglong2*)(sWg + k * 24);
        const ulonglong2 w0 = wr[0], w1 = wr[1], w2 = wr[2];
        fma2(accA[0], xi, w0.x); fma2(accA[1], xi, w0.y);
        fma2(accA[2], xi, w1.x); fma2(accA[3], xi, w1.y);
        fma2(accA[4], xi, w2.x); fma2(accA[5], xi, w2.y);
        fma2(accB[0], xj, w0.x); fma2(accB[1], xj, w0.y);
        fma2(accB[2], xj, w1.x); fma2(accB[3], xj, w1.y);
        fma2(accB[4], xj, w2.x); fma2(accB[5], xj, w2.y);
        const ulonglong2 w3 = wr[3], w4 = wr[4], w5 = wr[5];
        fma2(accA[6],  xi, w3.x); fma2(accA[7],  xi, w3.y);
        fma2(accA[8],  xi, w4.x); fma2(accA[9],  xi, w4.y);
        fma2(accA[10], xi, w5.x); fma2(accA[11], xi, w5.y);
        fma2(accB[6],  xj, w3.x); fma2(accB[7],  xj, w3.y);
        fma2(accB[8],  xj, w4.x); fma2(accB[9],  xj, w4.y);
        fma2(accB[10], xj, w5.x); fma2(accB[11], xj, w5.y);
    }

    // ---- attention dots, all 3 heads, both nodes ----
    float aSA[3], aDA[3], aSB[3], aDB[3];
    {
        const ulonglong2* S2 = (const ulonglong2*)sAttS;
        const ulonglong2* D2 = (const ulonglong2*)sAttD;
        #pragma unroll
        for (int hh = 0; hh < 3; hh++) {
            const ulonglong2 sa = S2[2*hh], sb = S2[2*hh + 1];
            const ulonglong2 da = D2[2*hh], db = D2[2*hh + 1];
            ull rSA = 0ull, rDA = 0ull, rSB = 0ull, rDB = 0ull;
            fma2(rSA, accA[4*hh],   sa.x); fma2(rSA, accA[4*hh+1], sa.y);
            fma2(rSA, accA[4*hh+2], sb.x); fma2(rSA, accA[4*hh+3], sb.y);
            fma2(rDA, accA[4*hh],   da.x); fma2(rDA, accA[4*hh+1], da.y);
            fma2(rDA, accA[4*hh+2], db.x); fma2(rDA, accA[4*hh+3], db.y);
            fma2(rSB, accB[4*hh],   sa.x); fma2(rSB, accB[4*hh+1], sa.y);
            fma2(rSB, accB[4*hh+2], sb.x); fma2(rSB, accB[4*hh+3], sb.y);
            fma2(rDB, accB[4*hh],   da.x); fma2(rDB, accB[4*hh+1], da.y);
            fma2(rDB, accB[4*hh+2], db.x); fma2(rDB, accB[4*hh+3], db.y);
            float2 f;
            f = unpack2(rSA); aSA[hh] = f.x + f.y;
            f = unpack2(rDA); aDA[hh] = f.x + f.y;
            f = unpack2(rSB); aSB[hh] = f.x + f.y;
            f = unpack2(rDB); aDB[hh] = f.x + f.y;
        }
    }

    // ---- publish h + a_src (only parent joints) ----
    if ((PARENT_MASK >> j) & 1u) {
        ulonglong2* r0 = (ulonglong2*)(sH + t * RS);
        ulonglong2* r1 = (ulonglong2*)(sH + (t + TPB) * RS);
        #pragma unroll
        for (int q = 0; q < 6; q++) {
            ulonglong2 va; va.x = accA[2*q]; va.y = accA[2*q + 1]; r0[q] = va;
            ulonglong2 vb; vb.x = accB[2*q]; vb.y = accB[2*q + 1]; r1[q] = vb;
        }
        float* f0 = sH + t * RS;
        float* f1 = sH + (t + TPB) * RS;
        f0[24] = aSA[0]; f0[25] = aSA[1]; f0[26] = aSA[2];
        f1[24] = aSB[0]; f1[25] = aSB[1]; f1[26] = aSB[2];
    }
    __syncthreads();

    // ---- epilogue ----
    const int par = c_parent[j];
    const bool hasPar = (par >= 0);
    const int pt = (t - j) + (hasPar ? par : j);

    ull bgp[12];
    {
        const ulonglong2* b2 = (const ulonglong2*)sbg;
        #pragma unroll
        for (int v = 0; v < 6; v++) { bgp[2*v] = b2[v].x; bgp[2*v + 1] = b2[v].y; }
    }

    finish_node(accA, aSA, aDA, sH + pt * RS,         hasPar, bgp, out + (base + (size_t)t) * 24);
    finish_node(accB, aSB, aDB, sH + (pt + TPB) * RS, hasPar, bgp, out + (base + (size_t)(t + TPB)) * 24);
}

extern "C" void kernel_launch(void* const* d_in, const int* in_sizes, int n_in,
                              void* d_out, int out_size) {
    (void)n_in; (void)out_size;
    const float* src  = (const float*)d_in[0];
    const float* Wpre = (const float*)d_in[1];
    const float* bpre = (const float*)d_in[2];
    const float* Wg   = (const float*)d_in[3];
    const float* attS = (const float*)d_in[4];
    const float* attD = (const float*)d_in[5];
    const float* bg   = (const float*)d_in[6];

    const int nodes  = in_sizes[0] / 3;   // 3,145,728
    const int blocks = nodes / NPB;       // 8,192 (exact)

    gat_encoder_kernel<<<blocks, TPB>>>(src, Wpre, bpre, Wg, attS, attD, bg, (float*)d_out);
}

// round 12
// speedup vs baseline: 1.3594x; 1.0464x over previous
#include <cuda_runtime.h>

#define NJ   24
#define TPB  192
#define NPB  (TPB * 2)     // 384 nodes = 16 frames per block; thread owns nodes t, t+192
#define RS   28            // sH row stride (floats): h[24] + a_src[3] + pad
#define NEG  0.2f

typedef unsigned long long ull;

__constant__ int c_parent[NJ] = {-1,0,0,0,1,2,3,4,5,6,7,8,9,9,9,12,13,14,16,17,18,19,20,21};
#define PARENT_MASK 0x3F73FFu   // joints that are some child's parent

__constant__ __align__(16) float cWg[576];   // Wg (24,24), filled per-launch via D2D memcpy node

__device__ __forceinline__ void fma2(ull &d, ull a, ull b) {
    asm("fma.rn.f32x2 %0, %1, %2, %0;" : "+l"(d) : "l"(a), "l"(b));
}
__device__ __forceinline__ ull pack2(float x) {
    ull r; asm("mov.b64 %0, {%1, %1};" : "=l"(r) : "f"(x)); return r;
}
__device__ __forceinline__ ull packf2(float lo, float hi) {
    ull r; asm("mov.b64 %0, {%1, %2};" : "=l"(r) : "f"(lo), "f"(hi)); return r;
}
__device__ __forceinline__ float2 unpack2(ull v) {
    float2 f; asm("mov.b64 {%0, %1}, %2;" : "=f"(f.x), "=f"(f.y) : "l"(v)); return f;
}

// epilogue for one node: 2-edge softmax + aggregate + bias + relu + store
__device__ __forceinline__ void finish_node(const ull* __restrict__ acc,   // 12 ch-pairs
                                            const float* __restrict__ aS,  // [3]
                                            const float* __restrict__ aD,  // [3]
                                            const float* __restrict__ prow,
                                            bool hasPar,
                                            const ull* __restrict__ bgp,   // 12 bias pairs
                                            float* __restrict__ outp)
{
    const ulonglong2* p2 = (const ulonglong2*)prow;
    ulonglong2 pr[6];
    #pragma unroll
    for (int q = 0; q < 6; q++) pr[q] = p2[q];         // parent h as 12 ch-pairs
    const float pasv[3] = {prow[24], prow[25], prow[26]};

    float alS[3], alP[3];
    #pragma unroll
    for (int hh = 0; hh < 3; hh++) {
        float es = aS[hh] + aD[hh];
        es = es >= 0.0f ? es : NEG * es;
        float ep = pasv[hh] + aD[hh];
        ep = ep >= 0.0f ? ep : NEG * ep;
        ep = hasPar ? ep : -1e30f;
        const float mx  = fmaxf(es, ep);
        const float ws  = __expf(es - mx);
        const float wp  = __expf(ep - mx);
        const float inv = __fdividef(1.0f, ws + wp);
        alS[hh] = ws * inv;
        alP[hh] = hasPar ? wp * inv : 0.0f;
    }

    float4* o4 = (float4*)outp;
    #pragma unroll
    for (int v = 0; v < 6; v++) {                       // 2 ch-pairs per float4
        const int q0 = 2*v, q1 = 2*v + 1;
        const int hh = v >> 1;
        const ull s2 = pack2(alS[hh]);
        const ull p2k = pack2(alP[hh]);
        ull o0 = bgp[q0], o1 = bgp[q1];
        const ull ph0 = (q0 & 1) ? pr[q0 >> 1].y : pr[q0 >> 1].x;
        const ull ph1 = (q1 & 1) ? pr[q1 >> 1].y : pr[q1 >> 1].x;
        fma2(o0, s2, acc[q0]); fma2(o0, p2k, ph0);
        fma2(o1, s2, acc[q1]); fma2(o1, p2k, ph1);
        const float2 f0 = unpack2(o0), f1 = unpack2(o1);
        float4 r;
        r.x = fmaxf(f0.x, 0.f); r.y = fmaxf(f0.y, 0.f);
        r.z = fmaxf(f1.x, 0.f); r.w = fmaxf(f1.y, 0.f);
        o4[v] = r;
    }
}

__global__ __launch_bounds__(TPB, 4)
void gat_encoder_kernel(const float* __restrict__ src,
                        const float* __restrict__ Wpre,   // (3,24)
                        const float* __restrict__ bpre,   // (24)
                        const float* __restrict__ Wg,     // (24,24)
                        const float* __restrict__ attS,   // (3,8)
                        const float* __restrict__ attD,   // (3,8)
                        const float* __restrict__ bg,     // (24)
                        float* __restrict__ out)
{
    __shared__ __align__(16) float sWgL[24 * 16]; // Wg channels 0..15, 64B rows
    __shared__ __align__(16) float sPre[96];      // per channel k: {w0, w1, w2, b}
    __shared__ __align__(16) float sAttS[24];
    __shared__ __align__(16) float sAttD[24];
    __shared__ __align__(16) float sbg[24];
    __shared__ __align__(16) float sH[NPB * RS];

    const int t = threadIdx.x;
    const int j = t % NJ;

    if (t < 96) {
        const int ch = t >> 2, r = t & 3;
        sPre[t] = (r < 3) ? Wpre[r * 24 + ch] : bpre[ch];
    }
    if (t < 24) { sAttS[t] = attS[t]; sAttD[t] = attD[t]; sbg[t] = bg[t]; }
    for (int i = t; i < 384; i += TPB) {
        const int row = i >> 4, c = i & 15;
        sWgL[i] = Wg[row * 24 + c];
    }

    const size_t base = (size_t)blockIdx.x * NPB;

    // ---- inputs: node pair (t, t+192) packed per input channel ----
    const float* pA = src + (base + (size_t)t) * 3;
    const float* pB = src + (base + (size_t)(t + TPB)) * 3;
    const float a0 = pA[0], a1 = pA[1], a2 = pA[2];
    const float b0 = pB[0], b1 = pB[1], b2 = pB[2];
    const ull pin0 = packf2(a0, b0);
    const ull pin1 = packf2(a1, b1);
    const ull pin2 = packf2(a2, b2);

    __syncthreads();

    // ---- fused: per k, x[k] for both nodes (one packed fma chain), feed 24-ch GEMM ----
    ull accA[12], accB[12];   // channel pairs for node t / node t+192
    #pragma unroll
    for (int q = 0; q < 12; q++) { accA[q] = 0ull; accB[q] = 0ull; }

    #pragma unroll
    for (int k = 0; k < 24; k++) {
        const float4 pw = ((const float4*)sPre)[k];    // {w0, w1, w2, b}
        ull xc = pack2(pw.w);                          // bias pair
        fma2(xc, pin0, pack2(pw.x));
        fma2(xc, pin1, pack2(pw.y));
        fma2(xc, pin2, pack2(pw.z));
        const float2 f = unpack2(xc);
        const ull xi = pack2(fmaxf(f.x, 0.0f));        // node t
        const ull xj = pack2(fmaxf(f.y, 0.0f));        // node t+192

        // channels 0..15 from shared (4 LDS.128)
        const ulonglong2* wr = (const ulonglong2*)(sWgL + k * 16);
        const ulonglong2 w0 = wr[0], w1 = wr[1], w2 = wr[2], w3 = wr[3];
        // channels 16..23 from constant cache (2 LDC.128, off the L1 port)
        const ulonglong2 w4 = *(const ulonglong2*)(cWg + k * 24 + 16);
        const ulonglong2 w5 = *(const ulonglong2*)(cWg + k * 24 + 20);

        fma2(accA[0], xi, w0.x); fma2(accA[1], xi, w0.y);
        fma2(accA[2], xi, w1.x); fma2(accA[3], xi, w1.y);
        fma2(accB[0], xj, w0.x); fma2(accB[1], xj, w0.y);
        fma2(accB[2], xj, w1.x); fma2(accB[3], xj, w1.y);
        fma2(accA[4], xi, w2.x); fma2(accA[5], xi, w2.y);
        fma2(accA[6], xi, w3.x); fma2(accA[7], xi, w3.y);
        fma2(accB[4], xj, w2.x); fma2(accB[5], xj, w2.y);
        fma2(accB[6], xj, w3.x); fma2(accB[7], xj, w3.y);
        fma2(accA[8],  xi, w4.x); fma2(accA[9],  xi, w4.y);
        fma2(accA[10], xi, w5.x); fma2(accA[11], xi, w5.y);
        fma2(accB[8],  xj, w4.x); fma2(accB[9],  xj, w4.y);
        fma2(accB[10], xj, w5.x); fma2(accB[11], xj, w5.y);
    }

    // ---- attention dots, all 3 heads, both nodes ----
    float aSA[3], aDA[3], aSB[3], aDB[3];
    {
        const ulonglong2* S2 = (const ulonglong2*)sAttS;
        const ulonglong2* D2 = (const ulonglong2*)sAttD;
        #pragma unroll
        for (int hh = 0; hh < 3; hh++) {
            const ulonglong2 sa = S2[2*hh], sb = S2[2*hh + 1];
            const ulonglong2 da = D2[2*hh], db = D2[2*hh + 1];
            ull rSA = 0ull, rDA = 0ull, rSB = 0ull, rDB = 0ull;
            fma2(rSA, accA[4*hh],   sa.x); fma2(rSA, accA[4*hh+1], sa.y);
            fma2(rSA, accA[4*hh+2], sb.x); fma2(rSA, accA[4*hh+3], sb.y);
            fma2(rDA, accA[4*hh],   da.x); fma2(rDA, accA[4*hh+1], da.y);
            fma2(rDA, accA[4*hh+2], db.x); fma2(rDA, accA[4*hh+3], db.y);
            fma2(rSB, accB[4*hh],   sa.x); fma2(rSB, accB[4*hh+1], sa.y);
            fma2(rSB, accB[4*hh+2], sb.x); fma2(rSB, accB[4*hh+3], sb.y);
            fma2(rDB, accB[4*hh],   da.x); fma2(rDB, accB[4*hh+1], da.y);
            fma2(rDB, accB[4*hh+2], db.x); fma2(rDB, accB[4*hh+3], db.y);
            float2 f;
            f = unpack2(rSA); aSA[hh] = f.x + f.y;
            f = unpack2(rDA); aDA[hh] = f.x + f.y;
            f = unpack2(rSB); aSB[hh] = f.x + f.y;
            f = unpack2(rDB); aDB[hh] = f.x + f.y;
        }
    }

    // ---- publish h + a_src (only parent joints) ----
    if ((PARENT_MASK >> j) & 1u) {
        ulonglong2* r0 = (ulonglong2*)(sH + t * RS);
        ulonglong2* r1 = (ulonglong2*)(sH + (t + TPB) * RS);
        #pragma unroll
        for (int q = 0; q < 6; q++) {
            ulonglong2 va; va.x = accA[2*q]; va.y = accA[2*q + 1]; r0[q] = va;
            ulonglong2 vb; vb.x = accB[2*q]; vb.y = accB[2*q + 1]; r1[q] = vb;
        }
        float* f0 = sH + t * RS;
        float* f1 = sH + (t + TPB) * RS;
        f0[24] = aSA[0]; f0[25] = aSA[1]; f0[26] = aSA[2];
        f1[24] = aSB[0]; f1[25] = aSB[1]; f1[26] = aSB[2];
    }
    __syncthreads();

    // ---- epilogue ----
    const int par = c_parent[j];
    const bool hasPar = (par >= 0);
    const int pt = (t - j) + (hasPar ? par : j);

    ull bgp[12];
    {
        const ulonglong2* b2 = (const ulonglong2*)sbg;
        #pragma unroll
        for (int v = 0; v < 6; v++) { bgp[2*v] = b2[v].x; bgp[2*v + 1] = b2[v].y; }
    }

    finish_node(accA, aSA, aDA, sH + pt * RS,         hasPar, bgp, out + (base + (size_t)t) * 24);
    finish_node(accB, aSB, aDB, sH + (pt + TPB) * RS, hasPar, bgp, out + (base + (size_t)(t + TPB)) * 24);
}

extern "C" void kernel_launch(void* const* d_in, const int* in_sizes, int n_in,
                              void* d_out, int out_size) {
    (void)n_in; (void)out_size;
    const float* src  = (const float*)d_in[0];
    const float* Wpre = (const float*)d_in[1];
    const float* bpre = (const float*)d_in[2];
    const float* Wg   = (const float*)d_in[3];
    const float* attS = (const float*)d_in[4];
    const float* attD = (const float*)d_in[5];
    const float* bg   = (const float*)d_in[6];

    // Wg -> constant bank (D2D memcpy node; graph-capturable, no allocation)
    cudaMemcpyToSymbolAsync(cWg, Wg, 576 * sizeof(float), 0, cudaMemcpyDeviceToDevice, 0);

    const int nodes  = in_sizes[0] / 3;   // 3,145,728
    const int blocks = nodes / NPB;       // 8,192 (exact)

    gat_encoder_kernel<<<blocks, TPB>>>(src, Wpre, bpre, Wg, attS, attD, bg, (float*)d_out);
}